// round 2
// baseline (speedup 1.0000x reference)
#include <cuda_runtime.h>

// DCN cross network, algebraically collapsed:
//   xi_{l+1} = x0 * (xi_l . w_l) + b_l + xi_l
// Since bias coefficients stay exactly 1 in xi_l = a_l*x0 + sum_{m<l} b_m:
//   s_l     = a_l * (x0 . w_l) + sum_{m<l} (b_m . w_l)
//   a_{l+1} = a_l + s_l,  a_0 = 1
//   out     = a_4 * x0 + (b_0+b_1+b_2+b_3)
// Row-dependent work: 4 simultaneous dots g_l = x0 . w_l (one reduction pass).
// Row-independent: c_{m,l} = b_m . w_l (6 scalars), bsum, transposed weights.

constexpr int D = 1024;
constexpr int THREADS = 256;  // 256 * 4 = D

__device__ float  g_c[6];        // c01,c02,c03,c12,c13,c23
__device__ float  g_bsum[D];     // b0+b1+b2+b3
__device__ float4 g_wt[D];       // {w0[e],w1[e],w2[e],w3[e]}

__global__ __launch_bounds__(1024) void precompute_kernel(
    const float* __restrict__ w, const float* __restrict__ b)
{
    const int e = threadIdx.x;           // 0..1023
    const int lane = e & 31, warp = e >> 5;

    float w0 = w[e], w1 = w[D + e], w2 = w[2 * D + e], w3 = w[3 * D + e];
    float b0 = b[e], b1 = b[D + e], b2 = b[2 * D + e], b3 = b[3 * D + e];

    g_wt[e] = make_float4(w0, w1, w2, w3);
    g_bsum[e] = ((b0 + b1) + (b2 + b3));

    float p[6] = { b0 * w1, b0 * w2, b0 * w3, b1 * w2, b1 * w3, b2 * w3 };

    __shared__ float red[32][6];
#pragma unroll
    for (int k = 0; k < 6; k++) {
#pragma unroll
        for (int o = 16; o > 0; o >>= 1)
            p[k] += __shfl_xor_sync(0xffffffffu, p[k], o);
        if (lane == 0) red[warp][k] = p[k];
    }
    __syncthreads();

    if (warp == 0) {
#pragma unroll
        for (int k = 0; k < 6; k++) {
            float v = red[lane][k];
#pragma unroll
            for (int o = 16; o > 0; o >>= 1)
                v += __shfl_xor_sync(0xffffffffu, v, o);
            if (lane == 0) g_c[k] = v;
        }
    }
}

__global__ __launch_bounds__(THREADS) void cross_network_kernel(
    const float* __restrict__ x, float* __restrict__ out)
{
    const int row = blockIdx.x;
    const int tid = threadIdx.x;
    const int lane = tid & 31, warp = tid >> 5;

    const float4* xrow = reinterpret_cast<const float4*>(x) + (size_t)row * (D / 4);
    float4 x0 = xrow[tid];

    // 4 simultaneous partial dots: g_l += x0[j] * wt[elem].l, elems 4*tid..4*tid+3
    float4 p = make_float4(0.f, 0.f, 0.f, 0.f);
#pragma unroll
    for (int j = 0; j < 4; j++) {
        float4 wt = g_wt[4 * tid + j];
        float xv = (j == 0) ? x0.x : (j == 1) ? x0.y : (j == 2) ? x0.z : x0.w;
        p.x = fmaf(xv, wt.x, p.x);
        p.y = fmaf(xv, wt.y, p.y);
        p.z = fmaf(xv, wt.z, p.z);
        p.w = fmaf(xv, wt.w, p.w);
    }

    // One reduction pass for all 4 dots
#pragma unroll
    for (int o = 16; o > 0; o >>= 1) {
        p.x += __shfl_xor_sync(0xffffffffu, p.x, o);
        p.y += __shfl_xor_sync(0xffffffffu, p.y, o);
        p.z += __shfl_xor_sync(0xffffffffu, p.z, o);
        p.w += __shfl_xor_sync(0xffffffffu, p.w, o);
    }

    __shared__ float4 red[THREADS / 32];
    if (lane == 0) red[warp] = p;
    __syncthreads();

    float4 g = red[0];
#pragma unroll
    for (int i = 1; i < THREADS / 32; i++) {
        float4 r = red[i];
        g.x += r.x; g.y += r.y; g.z += r.z; g.w += r.w;
    }

    // Scalar recurrence (uniform, row-independent constants from g_c)
    float c01 = g_c[0], c02 = g_c[1], c03 = g_c[2];
    float c12 = g_c[3], c13 = g_c[4], c23 = g_c[5];

    float a = 1.f;
    float s = a * g.x;                          a += s;   // layer 0
    s = fmaf(a, g.y, c01);                      a += s;   // layer 1
    s = fmaf(a, g.z, c02 + c12);                a += s;   // layer 2
    s = fmaf(a, g.w, c03 + (c13 + c23));        a += s;   // layer 3

    float4 bs = reinterpret_cast<const float4*>(g_bsum)[tid];
    float4 o;
    o.x = fmaf(a, x0.x, bs.x);
    o.y = fmaf(a, x0.y, bs.y);
    o.z = fmaf(a, x0.z, bs.z);
    o.w = fmaf(a, x0.w, bs.w);

    reinterpret_cast<float4*>(out)[(size_t)row * (D / 4) + tid] = o;
}

extern "C" void kernel_launch(void* const* d_in, const int* in_sizes, int n_in,
                              void* d_out, int out_size)
{
    const float* x = (const float*)d_in[0];
    const float* w = (const float*)d_in[1];
    const float* b = (const float*)d_in[2];
    float* out = (float*)d_out;

    const int batch = in_sizes[0] / D;  // 16384

    precompute_kernel<<<1, 1024>>>(w, b);
    cross_network_kernel<<<batch, THREADS>>>(x, out);
}

// round 4
// speedup vs baseline: 1.3600x; 1.3600x over previous
#include <cuda_runtime.h>

// DCN cross network, collapsed algebra + persistent CTAs.
//   xi_{l+1} = x0*(xi_l . w_l) + b_l + xi_l
//   xi_l = a_l*x0 + sum_{m<l} b_m  (bias coeffs provably stay 1)
//   s_l = a_l*(x0.w_l) + sum_{m<l}(b_m.w_l);  a_{l+1} = a_l + s_l
//   out = a_4*x0 + sum b_m
// Per row: 4 simultaneous dots g_l = x0.w_l, one reduction pass, scalar
// recurrence, one FMA epilogue. Constants (transposed weights, bias dots,
// bias sum) precomputed once and held in REGISTERS per persistent CTA.

constexpr int D = 1024;
constexpr int THREADS = 256;   // 256 * 4 = D
constexpr int GRID = 2048;     // 16384 / 2048 = 8 rows per CTA

__device__ float  g_c[6];        // b_m . w_l for m<l: c01,c02,c03,c12,c13,c23
__device__ float4 g_bsum4[D/4];  // b0+b1+b2+b3, packed float4
__device__ float4 g_wt[D];       // element e -> {w0[e],w1[e],w2[e],w3[e]}

__global__ __launch_bounds__(1024) void precompute_kernel(
    const float* __restrict__ w, const float* __restrict__ b)
{
    const int e = threadIdx.x;           // 0..1023
    const int lane = e & 31, warp = e >> 5;

    float w0 = w[e], w1 = w[D + e], w2 = w[2 * D + e], w3 = w[3 * D + e];
    float b0 = b[e], b1 = b[D + e], b2 = b[2 * D + e], b3 = b[3 * D + e];

    g_wt[e] = make_float4(w0, w1, w2, w3);
    reinterpret_cast<float*>(g_bsum4)[e] = (b0 + b1) + (b2 + b3);

    float p[6] = { b0 * w1, b0 * w2, b0 * w3, b1 * w2, b1 * w3, b2 * w3 };

    __shared__ float red[32][6];
#pragma unroll
    for (int k = 0; k < 6; k++) {
#pragma unroll
        for (int o = 16; o > 0; o >>= 1)
            p[k] += __shfl_xor_sync(0xffffffffu, p[k], o);
        if (lane == 0) red[warp][k] = p[k];
    }
    __syncthreads();

    if (warp == 0) {
#pragma unroll
        for (int k = 0; k < 6; k++) {
            float v = red[lane][k];
#pragma unroll
            for (int o = 16; o > 0; o >>= 1)
                v += __shfl_xor_sync(0xffffffffu, v, o);
            if (lane == 0) g_c[k] = v;
        }
    }
}

__global__ __launch_bounds__(THREADS) void cross_network_kernel(
    const float* __restrict__ x, float* __restrict__ out, int rows_per_cta)
{
    const int tid = threadIdx.x;
    const int lane = tid & 31, warp = tid >> 5;

    const float4* __restrict__ x4 = reinterpret_cast<const float4*>(x);
    float4* __restrict__ o4 = reinterpret_cast<float4*>(out);

    // Per-CTA constants, loaded ONCE, live in registers across all rows.
    const float4 wt0 = g_wt[4 * tid + 0];
    const float4 wt1 = g_wt[4 * tid + 1];
    const float4 wt2 = g_wt[4 * tid + 2];
    const float4 wt3 = g_wt[4 * tid + 3];
    const float4 bs  = g_bsum4[tid];
    const float c01 = g_c[0];
    const float k2 = g_c[1] + g_c[3];              // c02 + c12
    const float k3 = g_c[2] + (g_c[4] + g_c[5]);   // c03 + c13 + c23

    __shared__ float4 red[2][THREADS / 32];

    const int stride = gridDim.x;
    int row = blockIdx.x;

    float4 xa = x4[(size_t)row * (D / 4) + tid];

#pragma unroll 1
    for (int it = 0; it < rows_per_cta; it++) {
        // Prefetch next row while we reduce this one (last iter: reload same row,
        // harmless L1 hit, avoids a branch in the hot loop).
        const int nrow = (it + 1 < rows_per_cta) ? row + stride : row;
        float4 xb = x4[(size_t)nrow * (D / 4) + tid];

        // Partial dots for all 4 layers simultaneously.
        float4 p;
        p.x = xa.x * wt0.x; p.y = xa.x * wt0.y; p.z = xa.x * wt0.z; p.w = xa.x * wt0.w;
        p.x = fmaf(xa.y, wt1.x, p.x); p.y = fmaf(xa.y, wt1.y, p.y);
        p.z = fmaf(xa.y, wt1.z, p.z); p.w = fmaf(xa.y, wt1.w, p.w);
        p.x = fmaf(xa.z, wt2.x, p.x); p.y = fmaf(xa.z, wt2.y, p.y);
        p.z = fmaf(xa.z, wt2.z, p.z); p.w = fmaf(xa.z, wt2.w, p.w);
        p.x = fmaf(xa.w, wt3.x, p.x); p.y = fmaf(xa.w, wt3.y, p.y);
        p.z = fmaf(xa.w, wt3.z, p.z); p.w = fmaf(xa.w, wt3.w, p.w);

#pragma unroll
        for (int o = 16; o > 0; o >>= 1) {
            p.x += __shfl_xor_sync(0xffffffffu, p.x, o);
            p.y += __shfl_xor_sync(0xffffffffu, p.y, o);
            p.z += __shfl_xor_sync(0xffffffffu, p.z, o);
            p.w += __shfl_xor_sync(0xffffffffu, p.w, o);
        }
        const int par = it & 1;
        if (lane == 0) red[par][warp] = p;
        __syncthreads();   // single barrier per row (double-buffered red)

        float4 g = red[par][0];
#pragma unroll
        for (int i = 1; i < THREADS / 32; i++) {
            float4 r = red[par][i];
            g.x += r.x; g.y += r.y; g.z += r.z; g.w += r.w;
        }

        // Scalar recurrence
        float a = 1.f;
        float s = a * g.x;              a += s;   // layer 0
        s = fmaf(a, g.y, c01);          a += s;   // layer 1
        s = fmaf(a, g.z, k2);           a += s;   // layer 2
        s = fmaf(a, g.w, k3);           a += s;   // layer 3

        float4 o;
        o.x = fmaf(a, xa.x, bs.x);
        o.y = fmaf(a, xa.y, bs.y);
        o.z = fmaf(a, xa.z, bs.z);
        o.w = fmaf(a, xa.w, bs.w);
        o4[(size_t)row * (D / 4) + tid] = o;

        xa = xb;
        row = nrow;
    }
}

extern "C" void kernel_launch(void* const* d_in, const int* in_sizes, int n_in,
                              void* d_out, int out_size)
{
    const float* x = (const float*)d_in[0];
    const float* w = (const float*)d_in[1];
    const float* b = (const float*)d_in[2];
    float* out = (float*)d_out;

    const int batch = in_sizes[0] / D;  // 16384
    const int grid = (batch >= GRID && batch % GRID == 0) ? GRID : batch;
    const int rows_per_cta = batch / grid;

    precompute_kernel<<<1, 1024>>>(w, b);
    cross_network_kernel<<<grid, THREADS>>>(x, out, rows_per_cta);
}

// round 5
// speedup vs baseline: 1.7989x; 1.3227x over previous
#include <cuda_runtime.h>

// DCN cross network, collapsed algebra + warp-per-row (barrier-free).
//   xi_{l+1} = x0*(xi_l . w_l) + b_l + xi_l
//   xi_l = a_l*x0 + sum_{m<l} b_m   (bias coefficients provably stay 1)
//   s_l = a_l*(x0.w_l) + sum_{m<l}(b_m.w_l);  a_{l+1} = a_l + s_l;  a_0 = 1
//   out = a_4*x0 + sum_m b_m
// One WARP per row: 32 lanes x 32 elements. 4 simultaneous dots g_l = x0.w_l
// reduced in ONE warp-shuffle pass. No shared memory, no __syncthreads.
// Row-independent constants (3 scalars + bias sum) from a tiny precompute.

constexpr int D = 1024;
constexpr int THREADS = 256;           // 8 warps per CTA
constexpr int CHUNKS = D / 128;        // 8: each chunk = 128 elements (4/lane)

__device__ float  g_k[3];              // {c01, c02+c12, c03+c13+c23}
__device__ float4 g_bsum4[D / 4];      // b0+b1+b2+b3 packed float4

__global__ __launch_bounds__(1024) void precompute_kernel(
    const float* __restrict__ w, const float* __restrict__ b)
{
    const int e = threadIdx.x;         // 0..1023
    const int lane = e & 31, warp = e >> 5;

    float w1 = w[D + e], w2 = w[2 * D + e], w3 = w[3 * D + e];
    float b0 = b[e], b1 = b[D + e], b2 = b[2 * D + e], b3 = b[3 * D + e];

    reinterpret_cast<float*>(g_bsum4)[e] = (b0 + b1) + (b2 + b3);

    // k0 = b0.w1 ; k1 = (b0+b1).w2 ; k2 = (b0+b1+b2).w3
    float p0 = b0 * w1;
    float p1 = (b0 + b1) * w2;
    float p2 = ((b0 + b1) + b2) * w3;

    __shared__ float red[32][3];
#pragma unroll
    for (int o = 16; o > 0; o >>= 1) {
        p0 += __shfl_xor_sync(0xffffffffu, p0, o);
        p1 += __shfl_xor_sync(0xffffffffu, p1, o);
        p2 += __shfl_xor_sync(0xffffffffu, p2, o);
    }
    if (lane == 0) { red[warp][0] = p0; red[warp][1] = p1; red[warp][2] = p2; }
    __syncthreads();

    if (warp == 0 && lane < 3) {
        float v = 0.f;
#pragma unroll
        for (int i = 0; i < 32; i++) v += red[i][lane];
        g_k[lane] = v;
    }
}

__global__ __launch_bounds__(THREADS) void cross_network_kernel(
    const float* __restrict__ x, const float* __restrict__ w,
    float* __restrict__ out, int batch)
{
    const int lane = threadIdx.x & 31;
    const int row = blockIdx.x * (THREADS / 32) + (threadIdx.x >> 5);
    if (row >= batch) return;

    const float4* __restrict__ x4 = reinterpret_cast<const float4*>(x) +
                                    (size_t)row * (D / 4);
    const float4* __restrict__ w4 = reinterpret_cast<const float4*>(w);
    float4* __restrict__ o4 = reinterpret_cast<float4*>(out) +
                              (size_t)row * (D / 4);

    // Issue all 8 row loads upfront (MLP=8 per lane).
    float4 xs[CHUNKS];
#pragma unroll
    for (int j = 0; j < CHUNKS; j++)
        xs[j] = x4[j * 32 + lane];

    // Uniform scalars (L1/L2-hot broadcast), prefetched early.
    const float c01 = g_k[0], k2 = g_k[1], k3 = g_k[2];

    // Partial dots for all 4 layers. Chunk j covers elements j*128 + 4*lane..+3.
    // Weights read from ORIGINAL layout w[l][e]: float4 per layer, coalesced.
    float4 p = make_float4(0.f, 0.f, 0.f, 0.f);
#pragma unroll
    for (int j = 0; j < CHUNKS; j++) {
        const int eoff = j * 32 + lane;                 // float4 index within a row
        float4 w0 = w4[0 * (D / 4) + eoff];
        float4 w1 = w4[1 * (D / 4) + eoff];
        float4 w2 = w4[2 * (D / 4) + eoff];
        float4 w3 = w4[3 * (D / 4) + eoff];
        float4 xv = xs[j];
        p.x = fmaf(xv.x, w0.x, p.x); p.x = fmaf(xv.y, w0.y, p.x);
        p.x = fmaf(xv.z, w0.z, p.x); p.x = fmaf(xv.w, w0.w, p.x);
        p.y = fmaf(xv.x, w1.x, p.y); p.y = fmaf(xv.y, w1.y, p.y);
        p.y = fmaf(xv.z, w1.z, p.y); p.y = fmaf(xv.w, w1.w, p.y);
        p.z = fmaf(xv.x, w2.x, p.z); p.z = fmaf(xv.y, w2.y, p.z);
        p.z = fmaf(xv.z, w2.z, p.z); p.z = fmaf(xv.w, w2.w, p.z);
        p.w = fmaf(xv.x, w3.x, p.w); p.w = fmaf(xv.y, w3.y, p.w);
        p.w = fmaf(xv.z, w3.z, p.w); p.w = fmaf(xv.w, w3.w, p.w);
    }

    // One warp-shuffle reduction pass for all 4 dots. No smem, no barrier.
#pragma unroll
    for (int o = 16; o > 0; o >>= 1) {
        p.x += __shfl_xor_sync(0xffffffffu, p.x, o);
        p.y += __shfl_xor_sync(0xffffffffu, p.y, o);
        p.z += __shfl_xor_sync(0xffffffffu, p.z, o);
        p.w += __shfl_xor_sync(0xffffffffu, p.w, o);
    }

    // Scalar recurrence (uniform across warp).
    float a = 1.f + p.x;                       // layer 0
    float s = fmaf(a, p.y, c01);  a += s;      // layer 1
    s = fmaf(a, p.z, k2);         a += s;      // layer 2
    s = fmaf(a, p.w, k3);         a += s;      // layer 3

    // Epilogue: out = a * x0 + bsum
#pragma unroll
    for (int j = 0; j < CHUNKS; j++) {
        float4 bsv = g_bsum4[j * 32 + lane];
        float4 o;
        o.x = fmaf(a, xs[j].x, bsv.x);
        o.y = fmaf(a, xs[j].y, bsv.y);
        o.z = fmaf(a, xs[j].z, bsv.z);
        o.w = fmaf(a, xs[j].w, bsv.w);
        o4[j * 32 + lane] = o;
    }
}

extern "C" void kernel_launch(void* const* d_in, const int* in_sizes, int n_in,
                              void* d_out, int out_size)
{
    const float* x = (const float*)d_in[0];
    const float* w = (const float*)d_in[1];
    const float* b = (const float*)d_in[2];
    float* out = (float*)d_out;

    const int batch = in_sizes[0] / D;                 // 16384
    const int rows_per_cta = THREADS / 32;             // 8
    const int grid = (batch + rows_per_cta - 1) / rows_per_cta;

    precompute_kernel<<<1, 1024>>>(w, b);
    cross_network_kernel<<<grid, THREADS>>>(x, w, out, batch);
}

// round 9
// speedup vs baseline: 1.8490x; 1.0279x over previous
#include <cuda_runtime.h>

// DCN cross network, collapsed algebra + warp-per-row (barrier-free),
// register-lean for occupancy.
//   xi_{l+1} = x0*(xi_l . w_l) + b_l + xi_l
//   xi_l = a_l*x0 + sum_{m<l} b_m   (bias coefficients provably stay 1)
//   s_l = a_l*(x0.w_l) + sum_{m<l}(b_m.w_l);  a_{l+1} = a_l + s_l;  a_0 = 1
//   out = a_4*x0 + sum_m b_m
// One WARP per row: 32 lanes x 32 elements, one shuffle-reduction pass,
// no smem/barriers. x is re-loaded in the epilogue (L1-hot) instead of being
// held in 32 registers -> 5 CTAs/SM instead of 3.

constexpr int D = 1024;
constexpr int THREADS = 256;           // 8 warps per CTA
constexpr int CHUNKS = D / 128;        // 8 float4 per lane

__device__ float  g_k[3];              // {c01, c02+c12, c03+c13+c23}
__device__ float4 g_bsum4[D / 4];      // b0+b1+b2+b3 packed float4

__global__ __launch_bounds__(1024) void precompute_kernel(
    const float* __restrict__ w, const float* __restrict__ b)
{
    const int e = threadIdx.x;         // 0..1023
    const int lane = e & 31, warp = e >> 5;

    float w1 = w[D + e], w2 = w[2 * D + e], w3 = w[3 * D + e];
    float b0 = b[e], b1 = b[D + e], b2 = b[2 * D + e], b3 = b[3 * D + e];

    reinterpret_cast<float*>(g_bsum4)[e] = (b0 + b1) + (b2 + b3);

    // k0 = b0.w1 ; k1 = (b0+b1).w2 ; k2 = (b0+b1+b2).w3
    float p0 = b0 * w1;
    float p1 = (b0 + b1) * w2;
    float p2 = ((b0 + b1) + b2) * w3;

    __shared__ float red[32][3];
#pragma unroll
    for (int o = 16; o > 0; o >>= 1) {
        p0 += __shfl_xor_sync(0xffffffffu, p0, o);
        p1 += __shfl_xor_sync(0xffffffffu, p1, o);
        p2 += __shfl_xor_sync(0xffffffffu, p2, o);
    }
    if (lane == 0) { red[warp][0] = p0; red[warp][1] = p1; red[warp][2] = p2; }
    __syncthreads();

    if (warp == 0 && lane < 3) {
        float v = 0.f;
#pragma unroll
        for (int i = 0; i < 32; i++) v += red[i][lane];
        g_k[lane] = v;
    }
}

__global__ __launch_bounds__(THREADS, 5) void cross_network_kernel(
    const float* __restrict__ x, const float* __restrict__ w,
    float* __restrict__ out, int batch)
{
    const int lane = threadIdx.x & 31;
    const int row = blockIdx.x * (THREADS / 32) + (threadIdx.x >> 5);
    if (row >= batch) return;

    const float4* __restrict__ x4 = reinterpret_cast<const float4*>(x) +
                                    (size_t)row * (D / 4);
    const float4* __restrict__ w4 = reinterpret_cast<const float4*>(w);
    float4* __restrict__ o4 = reinterpret_cast<float4*>(out) +
                              (size_t)row * (D / 4);

    // Partial dots for all 4 layers. Chunk j covers float4 index j*32+lane.
    // x chunks are consumed immediately (not kept in registers).
    float4 p = make_float4(0.f, 0.f, 0.f, 0.f);
#pragma unroll
    for (int j = 0; j < CHUNKS; j++) {
        const int eoff = j * 32 + lane;
        float4 xv = x4[eoff];
        float4 w0 = w4[0 * (D / 4) + eoff];
        float4 w1 = w4[1 * (D / 4) + eoff];
        float4 w2 = w4[2 * (D / 4) + eoff];
        float4 w3 = w4[3 * (D / 4) + eoff];
        p.x = fmaf(xv.x, w0.x, p.x); p.x = fmaf(xv.y, w0.y, p.x);
        p.x = fmaf(xv.z, w0.z, p.x); p.x = fmaf(xv.w, w0.w, p.x);
        p.y = fmaf(xv.x, w1.x, p.y); p.y = fmaf(xv.y, w1.y, p.y);
        p.y = fmaf(xv.z, w1.z, p.y); p.y = fmaf(xv.w, w1.w, p.y);
        p.z = fmaf(xv.x, w2.x, p.z); p.z = fmaf(xv.y, w2.y, p.z);
        p.z = fmaf(xv.z, w2.z, p.z); p.z = fmaf(xv.w, w2.w, p.z);
        p.w = fmaf(xv.x, w3.x, p.w); p.w = fmaf(xv.y, w3.y, p.w);
        p.w = fmaf(xv.z, w3.z, p.w); p.w = fmaf(xv.w, w3.w, p.w);
    }

    // One warp-shuffle reduction pass for all 4 dots.
#pragma unroll
    for (int o = 16; o > 0; o >>= 1) {
        p.x += __shfl_xor_sync(0xffffffffu, p.x, o);
        p.y += __shfl_xor_sync(0xffffffffu, p.y, o);
        p.z += __shfl_xor_sync(0xffffffffu, p.z, o);
        p.w += __shfl_xor_sync(0xffffffffu, p.w, o);
    }

    // Scalar recurrence (uniform across warp).
    const float c01 = g_k[0], k2 = g_k[1], k3 = g_k[2];
    float a = 1.f + p.x;                       // layer 0
    float s = fmaf(a, p.y, c01);  a += s;      // layer 1
    s = fmaf(a, p.z, k2);         a += s;      // layer 2
    s = fmaf(a, p.w, k3);         a += s;      // layer 3

    // Epilogue: out = a * x0 + bsum.  x re-loaded (L1-hot from the dot pass).
#pragma unroll
    for (int j = 0; j < CHUNKS; j++) {
        const int eoff = j * 32 + lane;
        float4 xv = x4[eoff];
        float4 bsv = g_bsum4[eoff];
        float4 o;
        o.x = fmaf(a, xv.x, bsv.x);
        o.y = fmaf(a, xv.y, bsv.y);
        o.z = fmaf(a, xv.z, bsv.z);
        o.w = fmaf(a, xv.w, bsv.w);
        o4[eoff] = o;
    }
}

extern "C" void kernel_launch(void* const* d_in, const int* in_sizes, int n_in,
                              void* d_out, int out_size)
{
    const float* x = (const float*)d_in[0];
    const float* w = (const float*)d_in[1];
    const float* b = (const float*)d_in[2];
    float* out = (float*)d_out;

    const int batch = in_sizes[0] / D;                 // 16384
    const int rows_per_cta = THREADS / 32;             // 8
    const int grid = (batch + rows_per_cta - 1) / rows_per_cta;

    precompute_kernel<<<1, 1024>>>(w, b);
    cross_network_kernel<<<grid, THREADS>>>(x, w, out, batch);
}